// round 5
// baseline (speedup 1.0000x reference)
#include <cuda_runtime.h>

// Until operator: r[t] = max(min(1, psi[t]), min(phi[t], r[t+1])), r[T] = -inf.
// [B=1024, T=8192, C=2] fp32. Parallelized as a (max,min)-semiring scan with
// single-pass decoupled lookback across 1024-timestep segments.
//
// Op f_t(r) = max(v_t, min(p_t, r)), v_t = min(1, psi[t]).
// Compose (f earlier in time / outer, g later / inner):
//   P = min(Pf, Pg);  V = max(Vf, min(Pf, Vg)).
// min/max are exactly associative -> result is bit-exact regardless of grouping.
//
// R3: 256-thread blocks x 4 steps/thread. ~45 regs -> 5 blocks/SM (40 warps),
// desynchronized phases across blocks keep DRAM busy (R2: one 1024-thread
// block/SM => lockstep phases, DRAM 44%).

#define B_ROWS 1024
#define T_LEN  8192
#define BLK    256
#define STEPS  4
#define NF     (STEPS / 2)        // float4 chunks per array per thread
#define NW     (BLK / 32)         // warps per block (8)
#define SEG_TS (BLK * STEPS)      // 1024 timesteps per segment
#define SEGS   (T_LEN / SEG_TS)   // 8 segments per row
#define GRID   (B_ROWS * SEGS)    // 8192 blocks
#define ROW_F4 (T_LEN * 2 / 4)    // 4096 float4 per row
#define SEG_F4 (SEG_TS * 2 / 4)   // 512 float4 per segment

__device__ int    g_flag[GRID];   // 0 = none, 1 = aggregate ready, 2 = inclusive ready
__device__ float4 g_agg [GRID];   // (Px, Vx, Py, Vy)
__device__ float2 g_incl[GRID];   // (rx, ry) at segment's left boundary

__device__ __forceinline__ float finf()  { return __int_as_float(0x7f800000); }
__device__ __forceinline__ float fninf() { return __int_as_float(0xff800000); }

__global__ void reset_kernel() {
    int i = blockIdx.x * blockDim.x + threadIdx.x;
    if (i < GRID) g_flag[i] = 0;
}

__global__ void __launch_bounds__(BLK)
until_kernel(const float4* __restrict__ phi,
             const float4* __restrict__ psi,
             float4* __restrict__ out)
{
    const int bid  = blockIdx.x;
    const int row  = bid >> 3;
    const int sb   = bid & 7;               // segment index FROM THE BACK (0 = latest times)
    const int s    = (SEGS - 1) - sb;       // forward segment index
    const int tid  = threadIdx.x;
    const int lane = tid & 31;
    const int w    = tid >> 5;
    const size_t f0 = (size_t)row * ROW_F4 + (size_t)s * SEG_F4 + (size_t)tid * NF;

    // ---- Load chunk (phi raw; psi pre-clamped v = min(1, psi)) ----
    float4 p[NF], v[NF];
#pragma unroll
    for (int i = 0; i < NF; i++) {
        p[i] = phi[f0 + i];
        float4 q = psi[f0 + i];
        v[i].x = fminf(1.0f, q.x);
        v[i].y = fminf(1.0f, q.y);
        v[i].z = fminf(1.0f, q.z);
        v[i].w = fminf(1.0f, q.w);
    }
    // float4 layout: .x = ch0@t, .y = ch1@t, .z = ch0@t+1, .w = ch1@t+1

    // ---- Per-thread composed op (fold back-to-front) ----
    float Px = finf(), Vx = fninf();
    float Py = finf(), Vy = fninf();
#pragma unroll
    for (int i = NF - 1; i >= 0; i--) {
        Vx = fmaxf(v[i].z, fminf(p[i].z, Vx)); Px = fminf(p[i].z, Px);
        Vy = fmaxf(v[i].w, fminf(p[i].w, Vy)); Py = fminf(p[i].w, Py);
        Vx = fmaxf(v[i].x, fminf(p[i].x, Vx)); Px = fminf(p[i].x, Px);
        Vy = fmaxf(v[i].y, fminf(p[i].y, Vy)); Py = fminf(p[i].y, Py);
    }

    // ---- Warp-level reverse inclusive scan (Kogge-Stone over suffixes) ----
#pragma unroll
    for (int off = 1; off < 32; off <<= 1) {
        float Px2 = __shfl_down_sync(0xffffffffu, Px, off);
        float Vx2 = __shfl_down_sync(0xffffffffu, Vx, off);
        float Py2 = __shfl_down_sync(0xffffffffu, Py, off);
        float Vy2 = __shfl_down_sync(0xffffffffu, Vy, off);
        if (lane + off < 32) {
            Vx = fmaxf(Vx, fminf(Px, Vx2)); Px = fminf(Px, Px2);
            Vy = fmaxf(Vy, fminf(Py, Vy2)); Py = fminf(Py, Py2);
        }
    }
    // Exclusive within warp (suffix from lane+1); lane 31 = identity.
    float EPx = __shfl_down_sync(0xffffffffu, Px, 1);
    float EVx = __shfl_down_sync(0xffffffffu, Vx, 1);
    float EPy = __shfl_down_sync(0xffffffffu, Py, 1);
    float EVy = __shfl_down_sync(0xffffffffu, Vy, 1);
    if (lane == 31) { EPx = finf(); EVx = fninf(); EPy = finf(); EVy = fninf(); }

    __shared__ float4 wop[NW];
    __shared__ float2 scarry;
    if (lane == 0) wop[w] = make_float4(Px, Vx, Py, Vy);
    __syncthreads();

    // ---- Thread 0: block aggregate, publish, lookback for carry ----
    if (tid == 0) {
        // Block op = wop[0] o wop[1] o ... o wop[NW-1] (warp 0 = earliest time = outermost)
        float4 a = wop[NW - 1];
        float BPx = a.x, BVx = a.y, BPy = a.z, BVy = a.w;
#pragma unroll
        for (int j = NW - 2; j >= 0; j--) {
            float4 o = wop[j];
            BVx = fmaxf(o.y, fminf(o.x, BVx)); BPx = fminf(o.x, BPx);
            BVy = fmaxf(o.w, fminf(o.z, BVy)); BPy = fminf(o.z, BPy);
        }

        float cx = fninf(), cy = fninf();   // carry entering segment from the right
        if (sb > 0) {
            // Publish aggregate immediately so predecessors-in-bid (later lookers) can proceed.
            g_agg[bid] = make_float4(BPx, BVx, BPy, BVy);
            __threadfence();
            atomicExch(&g_flag[bid], 1);

            // Lookback over strictly smaller bids (later-time segments of this row).
            float Pax = finf(), Vax = fninf();
            float Pay = finf(), Vay = fninf();
            for (int j = bid - 1;; j--) {
                int f;
                do { f = *(volatile int*)&g_flag[j]; } while (f == 0);
                __threadfence();
                if (f == 2) {
                    float2 ic = *(float2*)&g_incl[j];   // written once before flag=2
                    float icx = ((volatile float2*)&g_incl[j])->x;  // force fresh read
                    float icy = ((volatile float2*)&g_incl[j])->y;
                    (void)ic;
                    cx = fmaxf(Vax, fminf(Pax, icx));
                    cy = fmaxf(Vay, fminf(Pay, icy));
                    break;
                } else {
                    float4 o;
                    o.x = ((volatile float4*)&g_agg[j])->x;
                    o.y = ((volatile float4*)&g_agg[j])->y;
                    o.z = ((volatile float4*)&g_agg[j])->z;
                    o.w = ((volatile float4*)&g_agg[j])->w;
                    // acc = acc o op_j (acc is outer / earlier-in-suffix-walk)
                    Vax = fmaxf(Vax, fminf(Pax, o.y)); Pax = fminf(Pax, o.x);
                    Vay = fmaxf(Vay, fminf(Pay, o.w)); Pay = fminf(Pay, o.z);
                }
            }
        }

        // Publish inclusive boundary value for earlier-time segments.
        if (sb < SEGS - 1) {
            float ix = fmaxf(BVx, fminf(BPx, cx));
            float iy = fmaxf(BVy, fminf(BPy, cy));
            g_incl[bid] = make_float2(ix, iy);
            __threadfence();
            atomicExch(&g_flag[bid], 2);
        }
        scarry = make_float2(cx, cy);
    }
    __syncthreads();

    // ---- Per-thread entering value: block carry -> later warps -> exclusive within warp ----
    float Ax = scarry.x, Ay = scarry.y;
    for (int j = NW - 1; j > w; j--) {
        float4 o = wop[j];
        Ax = fmaxf(o.y, fminf(o.x, Ax));
        Ay = fmaxf(o.w, fminf(o.z, Ay));
    }
    float rx = fmaxf(EVx, fminf(EPx, Ax));
    float ry = fmaxf(EVy, fminf(EPy, Ay));

    // ---- Backward sweep over register chunk; vectorized stores ----
#pragma unroll
    for (int i = NF - 1; i >= 0; i--) {
        rx = fmaxf(v[i].z, fminf(p[i].z, rx));
        ry = fmaxf(v[i].w, fminf(p[i].w, ry));
        float oz = rx, ow = ry;
        rx = fmaxf(v[i].x, fminf(p[i].x, rx));
        ry = fmaxf(v[i].y, fminf(p[i].y, ry));
        out[f0 + i] = make_float4(rx, ry, oz, ow);
    }
}

extern "C" void kernel_launch(void* const* d_in, const int* in_sizes, int n_in,
                              void* d_out, int out_size)
{
    const float4* phi = (const float4*)d_in[0];
    const float4* psi = (const float4*)d_in[1];
    float4*       o   = (float4*)d_out;
    reset_kernel<<<GRID / 1024, 1024>>>();
    until_kernel<<<GRID, BLK>>>(phi, psi, o);
}

// round 8
// speedup vs baseline: 1.5955x; 1.5955x over previous
#include <cuda_runtime.h>

// Until operator: r[t] = max(min(1, psi[t]), min(phi[t], r[t+1])), r[T] = -inf.
// [B=1024, T=8192, C=2] fp32. (max,min)-semiring reverse scan, exact.
//
// Op f_t(r) = max(v_t, min(p_t, r)), v_t = min(1, psi[t]).
// Compose (f earlier in time): P = min(Pf,Pg); V = max(Vf, min(Pf,Vg)).
//
// R8 (R6/R7 design, de-risked: no __ldcs/__stcs — those rounds died to
// container failures, never measured): one block per row, FULLY COALESCED.
// Thread t touches float4 i*BLK + tid -> every LDG.128/STG.128 hits the
// minimum 4 lines (R2's 64B/thread chunks hit 16 -> L1 wavefront queue was
// the hidden limiter). 8 iterations of block-wide reverse scan; carry lives
// in warp 0 registers; iteration i-1 loads issued before scanning i.

#define B_ROWS 1024
#define T_LEN  8192
#define BLK    512
#define ROW_F4 (T_LEN * 2 / 4)     // 4096 float4 per row
#define ITERS  (ROW_F4 / BLK)      // 8
#define NW     (BLK / 32)          // 16 warps

__device__ __forceinline__ float finf()  { return __int_as_float(0x7f800000); }
__device__ __forceinline__ float fninf() { return __int_as_float(0xff800000); }

__global__ void __launch_bounds__(BLK)
until_kernel(const float4* __restrict__ phi,
             const float4* __restrict__ psi,
             float4* __restrict__ out)
{
    const int    row  = blockIdx.x;
    const size_t base = (size_t)row * ROW_F4;
    const int    tid  = threadIdx.x;
    const int    lane = tid & 31;
    const int    w    = tid >> 5;

    __shared__ float4 wop[NW];      // per-warp composed op (Px,Vx,Py,Vy)
    __shared__ float2 warpin[NW];   // entering r value per warp

    // Prime: load the LAST (latest-time) iteration's data. Coalesced.
    float4 pc = phi[base + (ITERS - 1) * BLK + tid];
    float4 qc = psi[base + (ITERS - 1) * BLK + tid];

    float cx = fninf(), cy = fninf();   // inter-iteration carry (warp 0's copy is live)

#pragma unroll 1
    for (int i = ITERS - 1; i >= 0; --i) {
        // Prefetch next (earlier-time) iteration while we scan this one.
        float4 pn = make_float4(0.f, 0.f, 0.f, 0.f);
        float4 qn = make_float4(0.f, 0.f, 0.f, 0.f);
        if (i > 0) {
            pn = phi[base + (i - 1) * BLK + tid];
            qn = psi[base + (i - 1) * BLK + tid];
        }

        // v = min(1, psi). Layout: .x=ch0@t, .y=ch1@t, .z=ch0@t+1, .w=ch1@t+1
        const float vx = fminf(1.0f, qc.x), vy = fminf(1.0f, qc.y);
        const float vz = fminf(1.0f, qc.z), vw = fminf(1.0f, qc.w);

        // Pair op for this thread's 2 timesteps (t outer, t+1 inner).
        float Px = fminf(pc.x, pc.z);
        float Vx = fmaxf(vx, fminf(pc.x, vz));
        float Py = fminf(pc.y, pc.w);
        float Vy = fmaxf(vy, fminf(pc.y, vw));

        // Warp-level reverse inclusive scan (suffix compositions).
#pragma unroll
        for (int off = 1; off < 32; off <<= 1) {
            float Px2 = __shfl_down_sync(0xffffffffu, Px, off);
            float Vx2 = __shfl_down_sync(0xffffffffu, Vx, off);
            float Py2 = __shfl_down_sync(0xffffffffu, Py, off);
            float Vy2 = __shfl_down_sync(0xffffffffu, Vy, off);
            if (lane + off < 32) {
                Vx = fmaxf(Vx, fminf(Px, Vx2)); Px = fminf(Px, Px2);
                Vy = fmaxf(Vy, fminf(Py, Vy2)); Py = fminf(Py, Py2);
            }
        }
        // Exclusive within warp (suffix from lane+1); lane 31 = identity.
        float EPx = __shfl_down_sync(0xffffffffu, Px, 1);
        float EVx = __shfl_down_sync(0xffffffffu, Vx, 1);
        float EPy = __shfl_down_sync(0xffffffffu, Py, 1);
        float EVy = __shfl_down_sync(0xffffffffu, Vy, 1);
        if (lane == 31) { EPx = finf(); EVx = fninf(); EPy = finf(); EVy = fninf(); }

        // Lane 0's inclusive = whole-warp op.
        if (lane == 0) wop[w] = make_float4(Px, Vx, Py, Vy);
        __syncthreads();

        // Warp 0: scan the NW warp-ops, produce each warp's entering value,
        // and fold the block aggregate into the carry.
        if (w == 0) {
            float4 o = wop[lane & (NW - 1)];
            float WPx = o.x, WVx = o.y, WPy = o.z, WVy = o.w;
#pragma unroll
            for (int off = 1; off < NW; off <<= 1) {
                float P2 = __shfl_down_sync(0xffffffffu, WPx, off);
                float V2 = __shfl_down_sync(0xffffffffu, WVx, off);
                float P3 = __shfl_down_sync(0xffffffffu, WPy, off);
                float V3 = __shfl_down_sync(0xffffffffu, WVy, off);
                if (lane + off < NW) {
                    WVx = fmaxf(WVx, fminf(WPx, V2)); WPx = fminf(WPx, P2);
                    WVy = fmaxf(WVy, fminf(WPy, V3)); WPy = fminf(WPy, P3);
                }
            }
            // Exclusive warp-suffix; warp NW-1 gets identity.
            float XPx = __shfl_down_sync(0xffffffffu, WPx, 1);
            float XVx = __shfl_down_sync(0xffffffffu, WVx, 1);
            float XPy = __shfl_down_sync(0xffffffffu, WPy, 1);
            float XVy = __shfl_down_sync(0xffffffffu, WVy, 1);
            if (lane == NW - 1) { XPx = finf(); XVx = fninf(); XPy = finf(); XVy = fninf(); }

            if (lane < NW) {
                warpin[lane] = make_float2(fmaxf(XVx, fminf(XPx, cx)),
                                           fmaxf(XVy, fminf(XPy, cy)));
            }
            // Block aggregate = lane 0's inclusive; broadcast and update carry.
            float BPx = __shfl_sync(0xffffffffu, WPx, 0);
            float BVx = __shfl_sync(0xffffffffu, WVx, 0);
            float BPy = __shfl_sync(0xffffffffu, WPy, 0);
            float BVy = __shfl_sync(0xffffffffu, WVy, 0);
            cx = fmaxf(BVx, fminf(BPx, cx));
            cy = fmaxf(BVy, fminf(BPy, cy));
        }
        __syncthreads();

        // Entering value for this thread, then emit the two timesteps.
        float2 win = warpin[w];
        float rx = fmaxf(EVx, fminf(EPx, win.x));
        float ry = fmaxf(EVy, fminf(EPy, win.y));

        float oz = fmaxf(vz, fminf(pc.z, rx));   // t+1
        float ow = fmaxf(vw, fminf(pc.w, ry));
        float ox = fmaxf(vx, fminf(pc.x, oz));   // t
        float oy = fmaxf(vy, fminf(pc.y, ow));
        out[base + i * BLK + tid] = make_float4(ox, oy, oz, ow);

        pc = pn; qc = qn;
    }
}

extern "C" void kernel_launch(void* const* d_in, const int* in_sizes, int n_in,
                              void* d_out, int out_size)
{
    const float4* phi = (const float4*)d_in[0];
    const float4* psi = (const float4*)d_in[1];
    float4*       o   = (float4*)d_out;
    until_kernel<<<B_ROWS, BLK>>>(phi, psi, o);
}

// round 9
// speedup vs baseline: 1.7173x; 1.0764x over previous
#include <cuda_runtime.h>

// Until operator: r[t] = max(min(1, psi[t]), min(phi[t], r[t+1])), r[T] = -inf.
// [B=1024, T=8192, C=2] fp32. (max,min)-semiring reverse scan, exact.
//
// Op f_t(r) = max(v_t, min(p_t, r)), v_t = min(1, psi[t]).
// Compose (f earlier in time): P = min(Pf,Pg); V = max(Vf, min(Pf,Vg)).
//
// R9: R8 + scan amortization. Global access stays perfectly coalesced
// (thread t touches float4 seg+tid / seg+512+tid), but data is staged via
// padded smem so each thread scans 2 time-contiguous float4s (4 timesteps)
// per iteration -> ITERS 8->4, warp-scan/barrier cost per byte halved
// (R8: ALU 48.8% co-limited DRAM at 59%). Outputs staged back through smem
// so stores stay coalesced. Prefetch (4 LDG/thread) overlaps the scan.

#define B_ROWS 1024
#define T_LEN  8192
#define BLK    512
#define ROW_F4 (T_LEN * 2 / 4)     // 4096 float4 per row
#define ITERS  4
#define SEG_F4 (ROW_F4 / ITERS)    // 1024 float4 per segment
#define NW     (BLK / 32)          // 16 warps

// Padded smem index (float4 units): conflict-free for both linear writes
// and stride-2 float4 reads.
#define SPAD(i) ((i) + ((i) >> 3))
#define SMEM_F4 (SPAD(SEG_F4 - 1) + 1)   // 1151 -> round up
#define SMEM_SZ 1152

__device__ __forceinline__ float finf()  { return __int_as_float(0x7f800000); }
__device__ __forceinline__ float fninf() { return __int_as_float(0xff800000); }

__global__ void __launch_bounds__(BLK, 2)
until_kernel(const float4* __restrict__ phi,
             const float4* __restrict__ psi,
             float4* __restrict__ out)
{
    const int    row  = blockIdx.x;
    const size_t base = (size_t)row * ROW_F4;
    const int    tid  = threadIdx.x;
    const int    lane = tid & 31;
    const int    w    = tid >> 5;

    __shared__ float4 sp[SMEM_SZ];   // staged phi segment / staged outputs
    __shared__ float4 sq[SMEM_SZ];   // staged psi segment
    __shared__ float4 wop[NW];       // per-warp composed op (Px,Vx,Py,Vy)
    __shared__ float2 warpin[NW];    // entering r value per warp

    // Prologue: coalesced load of the LAST (latest-time) segment.
    float4 cp0 = phi[base + (ITERS - 1) * SEG_F4 + tid];
    float4 cp1 = phi[base + (ITERS - 1) * SEG_F4 + BLK + tid];
    float4 cq0 = psi[base + (ITERS - 1) * SEG_F4 + tid];
    float4 cq1 = psi[base + (ITERS - 1) * SEG_F4 + BLK + tid];

    float cx = fninf(), cy = fninf();   // inter-iteration carry (warp 0's copy live)

#pragma unroll 1
    for (int i = ITERS - 1; i >= 0; --i) {
        const size_t seg = base + (size_t)i * SEG_F4;

        // WAR guard vs previous iteration's output reads from sp.
        __syncthreads();

        // Stage current segment into padded smem (conflict-free linear writes).
        sp[SPAD(tid)]       = cp0;
        sp[SPAD(BLK + tid)] = cp1;
        sq[SPAD(tid)]       = cq0;
        sq[SPAD(BLK + tid)] = cq1;
        __syncthreads();

        // Each thread takes 2 time-contiguous float4s = timesteps 4t..4t+3.
        const int e0 = 2 * tid, e1 = 2 * tid + 1;
        float4 p0 = sp[SPAD(e0)];
        float4 p1 = sp[SPAD(e1)];
        float4 q0 = sq[SPAD(e0)];
        float4 q1 = sq[SPAD(e1)];

        // Prefetch next (earlier-time) segment; overlaps all scan work below.
        float4 np0 = make_float4(0.f,0.f,0.f,0.f), np1 = np0, nq0 = np0, nq1 = np0;
        if (i > 0) {
            const size_t nseg = seg - SEG_F4;
            np0 = phi[nseg + tid];
            np1 = phi[nseg + BLK + tid];
            nq0 = psi[nseg + tid];
            nq1 = psi[nseg + BLK + tid];
        }

        // v = min(1, psi). Layout: .x=ch0@t, .y=ch1@t, .z=ch0@t+1, .w=ch1@t+1
        const float v0x = fminf(1.f, q0.x), v0y = fminf(1.f, q0.y);
        const float v0z = fminf(1.f, q0.z), v0w = fminf(1.f, q0.w);
        const float v1x = fminf(1.f, q1.x), v1y = fminf(1.f, q1.y);
        const float v1z = fminf(1.f, q1.z), v1w = fminf(1.f, q1.w);

        // Per-thread composed op over 4 timesteps, folded back-to-front.
        // ch0 uses .x/.z, ch1 uses .y/.w.
        float Px = p1.z, Vx = v1z;
        float Py = p1.w, Vy = v1w;
        Vx = fmaxf(v1x, fminf(p1.x, Vx)); Px = fminf(p1.x, Px);
        Vy = fmaxf(v1y, fminf(p1.y, Vy)); Py = fminf(p1.y, Py);
        Vx = fmaxf(v0z, fminf(p0.z, Vx)); Px = fminf(p0.z, Px);
        Vy = fmaxf(v0w, fminf(p0.w, Vy)); Py = fminf(p0.w, Py);
        Vx = fmaxf(v0x, fminf(p0.x, Vx)); Px = fminf(p0.x, Px);
        Vy = fmaxf(v0y, fminf(p0.y, Vy)); Py = fminf(p0.y, Py);

        // Warp-level reverse inclusive scan (suffix compositions).
#pragma unroll
        for (int off = 1; off < 32; off <<= 1) {
            float Px2 = __shfl_down_sync(0xffffffffu, Px, off);
            float Vx2 = __shfl_down_sync(0xffffffffu, Vx, off);
            float Py2 = __shfl_down_sync(0xffffffffu, Py, off);
            float Vy2 = __shfl_down_sync(0xffffffffu, Vy, off);
            if (lane + off < 32) {
                Vx = fmaxf(Vx, fminf(Px, Vx2)); Px = fminf(Px, Px2);
                Vy = fmaxf(Vy, fminf(Py, Vy2)); Py = fminf(Py, Py2);
            }
        }
        // Exclusive within warp (suffix from lane+1); lane 31 = identity.
        float EPx = __shfl_down_sync(0xffffffffu, Px, 1);
        float EVx = __shfl_down_sync(0xffffffffu, Vx, 1);
        float EPy = __shfl_down_sync(0xffffffffu, Py, 1);
        float EVy = __shfl_down_sync(0xffffffffu, Vy, 1);
        if (lane == 31) { EPx = finf(); EVx = fninf(); EPy = finf(); EVy = fninf(); }

        if (lane == 0) wop[w] = make_float4(Px, Vx, Py, Vy);
        __syncthreads();

        // Warp 0: cross-warp scan of NW warp-ops, entering value per warp,
        // fold block aggregate into the carry.
        if (w == 0) {
            float4 o = wop[lane & (NW - 1)];
            float WPx = o.x, WVx = o.y, WPy = o.z, WVy = o.w;
#pragma unroll
            for (int off = 1; off < NW; off <<= 1) {
                float P2 = __shfl_down_sync(0xffffffffu, WPx, off);
                float V2 = __shfl_down_sync(0xffffffffu, WVx, off);
                float P3 = __shfl_down_sync(0xffffffffu, WPy, off);
                float V3 = __shfl_down_sync(0xffffffffu, WVy, off);
                if (lane + off < NW) {
                    WVx = fmaxf(WVx, fminf(WPx, V2)); WPx = fminf(WPx, P2);
                    WVy = fmaxf(WVy, fminf(WPy, V3)); WPy = fminf(WPy, P3);
                }
            }
            float XPx = __shfl_down_sync(0xffffffffu, WPx, 1);
            float XVx = __shfl_down_sync(0xffffffffu, WVx, 1);
            float XPy = __shfl_down_sync(0xffffffffu, WPy, 1);
            float XVy = __shfl_down_sync(0xffffffffu, WVy, 1);
            if (lane == NW - 1) { XPx = finf(); XVx = fninf(); XPy = finf(); XVy = fninf(); }

            if (lane < NW) {
                warpin[lane] = make_float2(fmaxf(XVx, fminf(XPx, cx)),
                                           fmaxf(XVy, fminf(XPy, cy)));
            }
            float BPx = __shfl_sync(0xffffffffu, WPx, 0);
            float BVx = __shfl_sync(0xffffffffu, WVx, 0);
            float BPy = __shfl_sync(0xffffffffu, WPy, 0);
            float BVy = __shfl_sync(0xffffffffu, WVy, 0);
            cx = fmaxf(BVx, fminf(BPx, cx));
            cy = fmaxf(BVy, fminf(BPy, cy));
        }
        __syncthreads();

        // Entering value for this thread, then sweep its 4 timesteps.
        float2 win = warpin[w];
        float rx = fmaxf(EVx, fminf(EPx, win.x));
        float ry = fmaxf(EVy, fminf(EPy, win.y));

        float4 o1, o0;
        o1.z = fmaxf(v1z, fminf(p1.z, rx));
        o1.w = fmaxf(v1w, fminf(p1.w, ry));
        o1.x = fmaxf(v1x, fminf(p1.x, o1.z));
        o1.y = fmaxf(v1y, fminf(p1.y, o1.w));
        o0.z = fmaxf(v0z, fminf(p0.z, o1.x));
        o0.w = fmaxf(v0w, fminf(p0.w, o1.y));
        o0.x = fmaxf(v0x, fminf(p0.x, o0.z));
        o0.y = fmaxf(v0y, fminf(p0.y, o0.w));

        // Stage outputs into sp (free after the wop barrier), then coalesced STG.
        sp[SPAD(e0)] = o0;
        sp[SPAD(e1)] = o1;
        __syncthreads();

        out[seg + tid]       = sp[SPAD(tid)];
        out[seg + BLK + tid] = sp[SPAD(BLK + tid)];

        cp0 = np0; cp1 = np1; cq0 = nq0; cq1 = nq1;
    }
}

extern "C" void kernel_launch(void* const* d_in, const int* in_sizes, int n_in,
                              void* d_out, int out_size)
{
    const float4* phi = (const float4*)d_in[0];
    const float4* psi = (const float4*)d_in[1];
    float4*       o   = (float4*)d_out;
    until_kernel<<<B_ROWS, BLK>>>(phi, psi, o);
}

// round 11
// speedup vs baseline: 1.8115x; 1.0548x over previous
#include <cuda_runtime.h>

// Until operator: r[t] = max(min(1, psi[t]), min(phi[t], r[t+1])), r[T] = -inf.
// [B=1024, T=8192, C=2] fp32. (max,min)-semiring reverse scan, exact.
//
// Op f_t(r) = max(v_t, min(p_t, r)), v_t = min(1, psi[t]).
// Compose (f earlier in time): P = min(Pf,Pg); V = max(Vf, min(Pf,Vg)).
//
// R11 (= R10 rebench; container failed twice on an unexotic kernel -> infra,
// same precedent as R6/R7->R8): R9 structure, BLK 512->256, 4 blocks/SM
// pinned. R8/R9 stalled at DRAM 58% with 2 lockstep blocks/SM — the
// barrier-serialized scan chain (~2x pure-BW time per iteration) left DRAM
// idle whenever both blocks were scanning. Same 32 warps/SM, but 4
// independent streams stagger load bursts against scan phases. Coalesced
// float4 access, padded-smem staging (4 timesteps/thread/iter),
// prefetch-ahead, staged stores all unchanged.

#define B_ROWS 1024
#define T_LEN  8192
#define BLK    256
#define ROW_F4 (T_LEN * 2 / 4)     // 4096 float4 per row
#define ITERS  8
#define SEG_F4 (ROW_F4 / ITERS)    // 512 float4 per segment
#define NW     (BLK / 32)          // 8 warps

// Padded smem index (float4 units): conflict-free for both linear writes
// and stride-2 float4 reads.
#define SPAD(i) ((i) + ((i) >> 3))
#define SMEM_SZ (SPAD(SEG_F4 - 1) + 2)

__device__ __forceinline__ float finf()  { return __int_as_float(0x7f800000); }
__device__ __forceinline__ float fninf() { return __int_as_float(0xff800000); }

__global__ void __launch_bounds__(BLK, 4)
until_kernel(const float4* __restrict__ phi,
             const float4* __restrict__ psi,
             float4* __restrict__ out)
{
    const int    row  = blockIdx.x;
    const size_t base = (size_t)row * ROW_F4;
    const int    tid  = threadIdx.x;
    const int    lane = tid & 31;
    const int    w    = tid >> 5;

    __shared__ float4 sp[SMEM_SZ];   // staged phi segment / staged outputs
    __shared__ float4 sq[SMEM_SZ];   // staged psi segment
    __shared__ float4 wop[NW];       // per-warp composed op (Px,Vx,Py,Vy)
    __shared__ float2 warpin[NW];    // entering r value per warp

    // Prologue: coalesced load of the LAST (latest-time) segment.
    float4 cp0 = phi[base + (ITERS - 1) * SEG_F4 + tid];
    float4 cp1 = phi[base + (ITERS - 1) * SEG_F4 + BLK + tid];
    float4 cq0 = psi[base + (ITERS - 1) * SEG_F4 + tid];
    float4 cq1 = psi[base + (ITERS - 1) * SEG_F4 + BLK + tid];

    float cx = fninf(), cy = fninf();   // inter-iteration carry (warp 0's copy live)

#pragma unroll 1
    for (int i = ITERS - 1; i >= 0; --i) {
        const size_t seg = base + (size_t)i * SEG_F4;

        // WAR guard vs previous iteration's output reads from sp.
        __syncthreads();

        // Stage current segment into padded smem (conflict-free linear writes).
        sp[SPAD(tid)]       = cp0;
        sp[SPAD(BLK + tid)] = cp1;
        sq[SPAD(tid)]       = cq0;
        sq[SPAD(BLK + tid)] = cq1;
        __syncthreads();

        // Each thread takes 2 time-contiguous float4s = timesteps 4t..4t+3.
        const int e0 = 2 * tid, e1 = 2 * tid + 1;
        float4 p0 = sp[SPAD(e0)];
        float4 p1 = sp[SPAD(e1)];
        float4 q0 = sq[SPAD(e0)];
        float4 q1 = sq[SPAD(e1)];

        // Prefetch next (earlier-time) segment; overlaps all scan work below.
        float4 np0 = make_float4(0.f,0.f,0.f,0.f), np1 = np0, nq0 = np0, nq1 = np0;
        if (i > 0) {
            const size_t nseg = seg - SEG_F4;
            np0 = phi[nseg + tid];
            np1 = phi[nseg + BLK + tid];
            nq0 = psi[nseg + tid];
            nq1 = psi[nseg + BLK + tid];
        }

        // v = min(1, psi). Layout: .x=ch0@t, .y=ch1@t, .z=ch0@t+1, .w=ch1@t+1
        const float v0x = fminf(1.f, q0.x), v0y = fminf(1.f, q0.y);
        const float v0z = fminf(1.f, q0.z), v0w = fminf(1.f, q0.w);
        const float v1x = fminf(1.f, q1.x), v1y = fminf(1.f, q1.y);
        const float v1z = fminf(1.f, q1.z), v1w = fminf(1.f, q1.w);

        // Per-thread composed op over 4 timesteps, folded back-to-front.
        float Px = p1.z, Vx = v1z;
        float Py = p1.w, Vy = v1w;
        Vx = fmaxf(v1x, fminf(p1.x, Vx)); Px = fminf(p1.x, Px);
        Vy = fmaxf(v1y, fminf(p1.y, Vy)); Py = fminf(p1.y, Py);
        Vx = fmaxf(v0z, fminf(p0.z, Vx)); Px = fminf(p0.z, Px);
        Vy = fmaxf(v0w, fminf(p0.w, Vy)); Py = fminf(p0.w, Py);
        Vx = fmaxf(v0x, fminf(p0.x, Vx)); Px = fminf(p0.x, Px);
        Vy = fmaxf(v0y, fminf(p0.y, Vy)); Py = fminf(p0.y, Py);

        // Warp-level reverse inclusive scan (suffix compositions).
#pragma unroll
        for (int off = 1; off < 32; off <<= 1) {
            float Px2 = __shfl_down_sync(0xffffffffu, Px, off);
            float Vx2 = __shfl_down_sync(0xffffffffu, Vx, off);
            float Py2 = __shfl_down_sync(0xffffffffu, Py, off);
            float Vy2 = __shfl_down_sync(0xffffffffu, Vy, off);
            if (lane + off < 32) {
                Vx = fmaxf(Vx, fminf(Px, Vx2)); Px = fminf(Px, Px2);
                Vy = fmaxf(Vy, fminf(Py, Vy2)); Py = fminf(Py, Py2);
            }
        }
        // Exclusive within warp (suffix from lane+1); lane 31 = identity.
        float EPx = __shfl_down_sync(0xffffffffu, Px, 1);
        float EVx = __shfl_down_sync(0xffffffffu, Vx, 1);
        float EPy = __shfl_down_sync(0xffffffffu, Py, 1);
        float EVy = __shfl_down_sync(0xffffffffu, Vy, 1);
        if (lane == 31) { EPx = finf(); EVx = fninf(); EPy = finf(); EVy = fninf(); }

        if (lane == 0) wop[w] = make_float4(Px, Vx, Py, Vy);
        __syncthreads();

        // Warp 0: cross-warp scan of NW warp-ops, entering value per warp,
        // fold block aggregate into the carry.
        if (w == 0) {
            float4 o = wop[lane & (NW - 1)];
            float WPx = o.x, WVx = o.y, WPy = o.z, WVy = o.w;
#pragma unroll
            for (int off = 1; off < NW; off <<= 1) {
                float P2 = __shfl_down_sync(0xffffffffu, WPx, off);
                float V2 = __shfl_down_sync(0xffffffffu, WVx, off);
                float P3 = __shfl_down_sync(0xffffffffu, WPy, off);
                float V3 = __shfl_down_sync(0xffffffffu, WVy, off);
                if (lane + off < NW) {
                    WVx = fmaxf(WVx, fminf(WPx, V2)); WPx = fminf(WPx, P2);
                    WVy = fmaxf(WVy, fminf(WPy, V3)); WPy = fminf(WPy, P3);
                }
            }
            float XPx = __shfl_down_sync(0xffffffffu, WPx, 1);
            float XVx = __shfl_down_sync(0xffffffffu, WVx, 1);
            float XPy = __shfl_down_sync(0xffffffffu, WPy, 1);
            float XVy = __shfl_down_sync(0xffffffffu, WVy, 1);
            if (lane == NW - 1) { XPx = finf(); XVx = fninf(); XPy = finf(); XVy = fninf(); }

            if (lane < NW) {
                warpin[lane] = make_float2(fmaxf(XVx, fminf(XPx, cx)),
                                           fmaxf(XVy, fminf(XPy, cy)));
            }
            float BPx = __shfl_sync(0xffffffffu, WPx, 0);
            float BVx = __shfl_sync(0xffffffffu, WVx, 0);
            float BPy = __shfl_sync(0xffffffffu, WPy, 0);
            float BVy = __shfl_sync(0xffffffffu, WVy, 0);
            cx = fmaxf(BVx, fminf(BPx, cx));
            cy = fmaxf(BVy, fminf(BPy, cy));
        }
        __syncthreads();

        // Entering value for this thread, then sweep its 4 timesteps.
        float2 win = warpin[w];
        float rx = fmaxf(EVx, fminf(EPx, win.x));
        float ry = fmaxf(EVy, fminf(EPy, win.y));

        float4 o1, o0;
        o1.z = fmaxf(v1z, fminf(p1.z, rx));
        o1.w = fmaxf(v1w, fminf(p1.w, ry));
        o1.x = fmaxf(v1x, fminf(p1.x, o1.z));
        o1.y = fmaxf(v1y, fminf(p1.y, o1.w));
        o0.z = fmaxf(v0z, fminf(p0.z, o1.x));
        o0.w = fmaxf(v0w, fminf(p0.w, o1.y));
        o0.x = fmaxf(v0x, fminf(p0.x, o0.z));
        o0.y = fmaxf(v0y, fminf(p0.y, o0.w));

        // Stage outputs into sp (free after the wop barrier), then coalesced STG.
        sp[SPAD(e0)] = o0;
        sp[SPAD(e1)] = o1;
        __syncthreads();

        out[seg + tid]       = sp[SPAD(tid)];
        out[seg + BLK + tid] = sp[SPAD(BLK + tid)];

        cp0 = np0; cp1 = np1; cq0 = nq0; cq1 = nq1;
    }
}

extern "C" void kernel_launch(void* const* d_in, const int* in_sizes, int n_in,
                              void* d_out, int out_size)
{
    const float4* phi = (const float4*)d_in[0];
    const float4* psi = (const float4*)d_in[1];
    float4*       o   = (float4*)d_out;
    until_kernel<<<B_ROWS, BLK>>>(phi, psi, o);
}